// round 6
// baseline (speedup 1.0000x reference)
#include <cuda_runtime.h>
#include <cstdint>
#include <cstddef>

#define SEQ   512
#define BATCH 64
#define INDIM 128
#define HDIM  512

#define CL    8            // CTAs per cluster (H split)
#define NG    16           // batch groups = clusters
#define BROWS 4            // batch rows per group (64/16)
#define JC    (HDIM / CL)  // 64 j columns per CTA
#define RT    256
#define TX_BYTES (BROWS * HDIM * 4)   // 8192 bytes arriving per step

typedef unsigned long long u64;

__device__ __forceinline__ u64 fma2(u64 a, u64 b, u64 c) {
    u64 d;
    asm("fma.rn.f32x2 %0, %1, %2, %3;" : "=l"(d) : "l"(a), "l"(b), "l"(c));
    return d;
}
__device__ __forceinline__ uint32_t smem_u32(const void* p) {
    uint32_t a;
    asm("{ .reg .u64 t; cvta.to.shared.u64 t, %1; cvt.u32.u64 %0, t; }" : "=r"(a) : "l"(p));
    return a;
}
__device__ __forceinline__ uint32_t mapa_u32(uint32_t a, uint32_t r) {
    uint32_t d;
    asm("mapa.shared::cluster.u32 %0, %1, %2;" : "=r"(d) : "r"(a), "r"(r));
    return d;
}
__device__ __forceinline__ void mbar_init(uint32_t a, uint32_t cnt) {
    asm volatile("mbarrier.init.shared.b64 [%0], %1;" :: "r"(a), "r"(cnt) : "memory");
}
__device__ __forceinline__ void mbar_arrive_expect_tx(uint32_t a, uint32_t tx) {
    asm volatile("mbarrier.arrive.expect_tx.shared.b64 _, [%0], %1;"
                 :: "r"(a), "r"(tx) : "memory");
}
__device__ __forceinline__ void mbar_wait(uint32_t a, uint32_t parity) {
    asm volatile(
        "{\n\t"
        ".reg .pred P;\n\t"
        "WL_%=:\n\t"
        "mbarrier.try_wait.parity.acquire.cta.shared::cta.b64 P, [%0], %1, 0x989680;\n\t"
        "@P bra.uni WD_%=;\n\t"
        "bra.uni WL_%=;\n\t"
        "WD_%=:\n\t"
        "}"
        :: "r"(a), "r"(parity) : "memory");
}
// remote SMEM store + tx-count delivery to the peer's mbarrier (one instr)
__device__ __forceinline__ void st_async_b64(uint32_t dst, u64 v, uint32_t mbar) {
    asm volatile("st.async.weak.shared::cluster.mbarrier::complete_tx::bytes.b64 [%0], %1, [%2];"
                 :: "r"(dst), "l"(v), "r"(mbar) : "memory");
}
#define CLUSTER_SYNC() do { \
    asm volatile("barrier.cluster.arrive.aligned;" ::: "memory"); \
    asm volatile("barrier.cluster.wait.aligned;"   ::: "memory"); \
} while (0)

// ---------------------------------------------------------------------------
// xi kernel: out[s][b][h] = x[s][b][:] . Wi[h][:] + bi[h] + bh[h]
// ---------------------------------------------------------------------------
__global__ __launch_bounds__(256) void xi_kernel(
    const float* __restrict__ x, const float* __restrict__ Wi,
    const float* __restrict__ bi, const float* __restrict__ bh,
    float* __restrict__ out)
{
    extern __shared__ float sm[];
    float* ws = sm;               // [128][130]
    float* xs = sm + 128 * 130;   // [64][130]

    const int tid = threadIdx.x;
    const int sb0 = blockIdx.x * 64;
    const int h0  = blockIdx.y * 128;

    for (int i = tid; i < 128 * INDIM; i += 256) {
        int r = i >> 7, k = i & 127;
        ws[r * 130 + k] = Wi[(h0 + r) * INDIM + k];
    }
    for (int i = tid; i < 64 * INDIM; i += 256) {
        int r = i >> 7, k = i & 127;
        xs[r * 130 + k] = x[(size_t)(sb0 + r) * INDIM + k];
    }
    __syncthreads();

    const int w  = tid >> 5;
    const int tx = tid & 31;

    u64 acc2[8][4];
#pragma unroll
    for (int i = 0; i < 8; i++)
#pragma unroll
        for (int j = 0; j < 4; j++) acc2[i][j] = 0ull;

    const u64* xb2 = (const u64*)xs + (w * 8) * 65;
    const u64* wb2 = (const u64*)ws;

#pragma unroll 4
    for (int kp = 0; kp < 64; kp++) {
        u64 xv[8], wv[4];
#pragma unroll
        for (int i = 0; i < 8; i++) xv[i] = xb2[i * 65 + kp];
#pragma unroll
        for (int j = 0; j < 4; j++) wv[j] = wb2[(j * 32 + tx) * 65 + kp];
#pragma unroll
        for (int i = 0; i < 8; i++)
#pragma unroll
            for (int j = 0; j < 4; j++) acc2[i][j] = fma2(xv[i], wv[j], acc2[i][j]);
    }

#pragma unroll
    for (int j = 0; j < 4; j++) {
        int h = h0 + j * 32 + tx;
        float b = bi[h] + bh[h];
#pragma unroll
        for (int i = 0; i < 8; i++) {
            float2 a = *reinterpret_cast<float2*>(&acc2[i][j]);
            out[(size_t)(sb0 + w * 8 + i) * HDIM + h] = a.x + a.y + b;
        }
    }
}

// ---------------------------------------------------------------------------
// Persistent recurrence: 16 clusters (4 batch rows each) x 8 CTAs (64 j-cols).
// Wh tile [64][512] (128KB) SMEM-resident. Per step, each CTA computes its
// h-chunk from the LOCAL full-h copy, then st.async-pushes packed b64 pairs
// into all 8 peers' ping-pong hbuf with complete_tx on the peers' mbarriers.
// Consumer wait = one try_wait.parity (fires when last byte lands). No
// cluster barrier, no L1 flush, no global-store drain on the chain.
// ---------------------------------------------------------------------------
__global__ __launch_bounds__(RT, 1) __cluster_dims__(CL, 1, 1)
void rnn_kernel(const float* __restrict__ Wh, float* __restrict__ out)
{
    extern __shared__ float sm[];
    float* sWh  = sm;                              // [JC][HDIM]       128 KB
    float* hbuf = sm + JC * HDIM;                  // [2][BROWS][HDIM]  16 KB
    u64*   mbar = (u64*)(sm + JC * HDIM + 2 * BROWS * HDIM);  // full[2]

    const int tid = threadIdx.x;
    uint32_t rank;
    asm("mov.u32 %0, %%cluster_ctarank;" : "=r"(rank));
    const int g = blockIdx.x / CL;

    if (tid == 0) {
        mbar_init(smem_u32(&mbar[0]), 1);
        mbar_init(smem_u32(&mbar[1]), 1);
    }

    // load this CTA's Wh rows [rank*JC, +JC) once
    {
        const float4* src = (const float4*)(Wh + (size_t)rank * JC * HDIM);
        float4* dst = (float4*)sWh;
        for (int i = tid; i < JC * HDIM / 4; i += RT) dst[i] = src[i];
    }
    __syncthreads();
    CLUSTER_SYNC();   // peers' mbarriers initialized before any st.async

    const int w    = tid >> 5;
    const int lane = tid & 31;
    const int b    = lane >> 3;
    const int ojl  = rank * JC + w * 8 + (lane & 7);
    const int ob   = g * BROWS + b;

    const u64* wb2 = (const u64*)sWh + (w * 8) * (HDIM / 2) + lane;

    const uint32_t hb_base = smem_u32(hbuf);
    const uint32_t mb_base = smem_u32(mbar);
    uint32_t peer_hb[CL], peer_mb[CL];
#pragma unroll
    for (int r = 0; r < CL; r++) {
        uint32_t pr = (rank + r) & (CL - 1);
        peer_hb[r] = mapa_u32(hb_base, pr);
        peer_mb[r] = mapa_u32(mb_base, pr);
    }

    int ph[2] = {0, 0};   // wait-parity per buffer

    // xi double-prefetch (xi' = xi + bi + bh, precomputed by xi_kernel)
    const size_t obase = (size_t)ob * HDIM + ojl;
    float xiv_next = __ldg(out + obase);

    for (int t = 1; t <= SEQ; t++) {
        const int bcur = t & 1;
        const size_t oidx = (size_t)(t - 1) * (BATCH * HDIM) + obase;

        // post expected tx for the h_t pushes arriving at our mb[bcur]
        if (t < SEQ && tid == 0) mbar_arrive_expect_tx(mb_base + bcur * 8, TX_BYTES);

        const float xiv = xiv_next;
        if (t < SEQ) xiv_next = __ldg(out + oidx + BATCH * HDIM);

        float sum = 0.f;
        if (t > 1) {
            const int bprev = (t - 1) & 1;
            mbar_wait(mb_base + bprev * 8, ph[bprev]);
            ph[bprev] ^= 1;

            const u64* hp = (const u64*)(hbuf + bprev * BROWS * HDIM) + lane;

            u64 acc[4][8];
#pragma unroll
            for (int i = 0; i < 4; i++)
#pragma unroll
                for (int j = 0; j < 8; j++) acc[i][j] = 0ull;

#pragma unroll
            for (int d = 0; d < 8; d++) {
                u64 hv[4], wv[8];
#pragma unroll
                for (int i = 0; i < 4; i++) hv[i] = hp[i * (HDIM / 2) + d * 32];
#pragma unroll
                for (int j = 0; j < 8; j++) wv[j] = wb2[j * (HDIM / 2) + d * 32];
#pragma unroll
                for (int i = 0; i < 4; i++)
#pragma unroll
                    for (int j = 0; j < 8; j++) acc[i][j] = fma2(hv[i], wv[j], acc[i][j]);
            }

            float v[32];
#pragma unroll
            for (int i = 0; i < 4; i++)
#pragma unroll
                for (int j = 0; j < 8; j++) {
                    float2 a = *reinterpret_cast<float2*>(&acc[i][j]);
                    v[i * 8 + j] = a.x + a.y;
                }
#pragma unroll
            for (int m = 0; m < 5; m++) {
                const int mb2 = (lane >> m) & 1;
#pragma unroll
                for (int j2 = 0; j2 < (16 >> m); j2++) {
                    float send = v[2 * j2 + 1 - mb2];
                    float recv = __shfl_xor_sync(0xffffffffu, send, 1 << m);
                    v[j2] = v[2 * j2 + mb2] + recv;
                }
            }
            sum = v[0];
        }

        const float hval = tanhf(sum + xiv);

        // push first (critical path), bookkeeping stores after
        float nxt = __shfl_down_sync(0xffffffffu, hval, 1);
        if (t < SEQ && !(lane & 1)) {
            float2 p2 = make_float2(hval, nxt);
            u64 pv = *reinterpret_cast<u64*>(&p2);
            const uint32_t off = (uint32_t)((bcur * BROWS * HDIM + b * HDIM + ojl) * 4);
            const uint32_t mboff = bcur * 8;
#pragma unroll
            for (int r = 0; r < CL; r++)
                st_async_b64(peer_hb[r] + off, pv, peer_mb[r] + mboff);
        }

        out[oidx] = hval;   // h_seq[t-1], off the dependency chain
        if (t == SEQ)
            out[(size_t)SEQ * BATCH * HDIM + obase] = hval;   // h_last
    }
}

// ---------------------------------------------------------------------------
extern "C" void kernel_launch(void* const* d_in, const int* in_sizes, int n_in,
                              void* d_out, int out_size)
{
    const float* x  = (const float*)d_in[0];
    const float* Wi = (const float*)d_in[1];
    const float* bi = (const float*)d_in[2];
    const float* Wh = (const float*)d_in[3];
    const float* bh = (const float*)d_in[4];
    float* out = (float*)d_out;

    const int XI_SMEM  = (128 * 130 + 64 * 130) * 4;                 // 99840 B
    const int RNN_SMEM = (JC * HDIM + 2 * BROWS * HDIM) * 4 + 16;    // 147472 B

    cudaFuncSetAttribute(xi_kernel,  cudaFuncAttributeMaxDynamicSharedMemorySize, XI_SMEM);
    cudaFuncSetAttribute(rnn_kernel, cudaFuncAttributeMaxDynamicSharedMemorySize, RNN_SMEM);

    xi_kernel<<<dim3(32768 / 64, HDIM / 128), 256, XI_SMEM>>>(x, Wi, bi, bh, out);
    rnn_kernel<<<NG * CL, RT, RNN_SMEM>>>(Wh, out);
}

// round 8
// speedup vs baseline: 1.8481x; 1.8481x over previous
#include <cuda_runtime.h>
#include <cstdint>
#include <cstddef>

#define SEQ   512
#define BATCH 64
#define INDIM 128
#define HDIM  512

#define CL    8            // CTAs per cluster (H split)
#define NG    16           // batch groups = clusters
#define BROWS 4            // batch rows per group (64/16)
#define JC    (HDIM / CL)  // 64 j columns per CTA
#define RT    256

typedef unsigned long long u64;

__device__ __forceinline__ u64 fma2(u64 a, u64 b, u64 c) {
    u64 d;
    asm("fma.rn.f32x2 %0, %1, %2, %3;" : "=l"(d) : "l"(a), "l"(b), "l"(c));
    return d;
}
__device__ __forceinline__ uint32_t smem_u32(const void* p) {
    uint32_t a;
    asm("{ .reg .u64 t; cvta.to.shared.u64 t, %1; cvt.u32.u64 %0, t; }" : "=r"(a) : "l"(p));
    return a;
}
__device__ __forceinline__ uint32_t mapa_u32(uint32_t a, uint32_t r) {
    uint32_t d;
    asm("mapa.shared::cluster.u32 %0, %1, %2;" : "=r"(d) : "r"(a), "r"(r));
    return d;
}
__device__ __forceinline__ void mbar_init(uint32_t a, uint32_t cnt) {
    asm volatile("mbarrier.init.shared.b64 [%0], %1;" :: "r"(a), "r"(cnt) : "memory");
}
// wait on OWN barrier with cluster-scope acquire (remote producers' stores)
__device__ __forceinline__ void mbar_wait_cluster(uint32_t a, uint32_t parity) {
    asm volatile(
        "{\n\t"
        ".reg .pred P;\n\t"
        "WL_%=:\n\t"
        "mbarrier.try_wait.parity.acquire.cluster.shared::cta.b64 P, [%0], %1, 0x989680;\n\t"
        "@P bra.uni WD_%=;\n\t"
        "bra.uni WL_%=;\n\t"
        "WD_%=:\n\t"
        "}"
        :: "r"(a), "r"(parity) : "memory");
}
// one remote arrive (release, cluster scope) on a peer's mbarrier
__device__ __forceinline__ void mbar_arrive_remote(uint32_t a) {
    asm volatile("mbarrier.arrive.release.cluster.shared::cluster.b64 _, [%0];"
                 :: "r"(a) : "memory");
}
__device__ __forceinline__ void fence_cluster() {
    asm volatile("fence.acq_rel.cluster;" ::: "memory");
}
__device__ __forceinline__ void st_cluster_b64(uint32_t a, u64 v) {
    asm volatile("st.shared::cluster.b64 [%0], %1;" :: "r"(a), "l"(v) : "memory");
}
#define CLUSTER_SYNC() do { \
    asm volatile("barrier.cluster.arrive.aligned;" ::: "memory"); \
    asm volatile("barrier.cluster.wait.aligned;"   ::: "memory"); \
} while (0)

// ---------------------------------------------------------------------------
// xi kernel: out[s][b][h] = x[s][b][:] . Wi[h][:] + bi[h] + bh[h]
// ---------------------------------------------------------------------------
__global__ __launch_bounds__(256) void xi_kernel(
    const float* __restrict__ x, const float* __restrict__ Wi,
    const float* __restrict__ bi, const float* __restrict__ bh,
    float* __restrict__ out)
{
    extern __shared__ float sm[];
    float* ws = sm;               // [128][130]
    float* xs = sm + 128 * 130;   // [64][130]

    const int tid = threadIdx.x;
    const int sb0 = blockIdx.x * 64;
    const int h0  = blockIdx.y * 128;

    for (int i = tid; i < 128 * INDIM; i += 256) {
        int r = i >> 7, k = i & 127;
        ws[r * 130 + k] = Wi[(h0 + r) * INDIM + k];
    }
    for (int i = tid; i < 64 * INDIM; i += 256) {
        int r = i >> 7, k = i & 127;
        xs[r * 130 + k] = x[(size_t)(sb0 + r) * INDIM + k];
    }
    __syncthreads();

    const int w  = tid >> 5;
    const int tx = tid & 31;

    u64 acc2[8][4];
#pragma unroll
    for (int i = 0; i < 8; i++)
#pragma unroll
        for (int j = 0; j < 4; j++) acc2[i][j] = 0ull;

    const u64* xb2 = (const u64*)xs + (w * 8) * 65;
    const u64* wb2 = (const u64*)ws;

#pragma unroll 4
    for (int kp = 0; kp < 64; kp++) {
        u64 xv[8], wv[4];
#pragma unroll
        for (int i = 0; i < 8; i++) xv[i] = xb2[i * 65 + kp];
#pragma unroll
        for (int j = 0; j < 4; j++) wv[j] = wb2[(j * 32 + tx) * 65 + kp];
#pragma unroll
        for (int i = 0; i < 8; i++)
#pragma unroll
            for (int j = 0; j < 4; j++) acc2[i][j] = fma2(xv[i], wv[j], acc2[i][j]);
    }

#pragma unroll
    for (int j = 0; j < 4; j++) {
        int h = h0 + j * 32 + tx;
        float b = bi[h] + bh[h];
#pragma unroll
        for (int i = 0; i < 8; i++) {
            float2 a = *reinterpret_cast<float2*>(&acc2[i][j]);
            out[(size_t)(sb0 + w * 8 + i) * HDIM + h] = a.x + a.y + b;
        }
    }
}

// ---------------------------------------------------------------------------
// Persistent recurrence: 16 clusters (4 batch rows) x 8 CTAs (64 j-cols).
// Wh tile [64][512] (128KB) SMEM-resident. Per step: compute own h-chunk from
// LOCAL full-h copy; even lanes push packed b64 pairs to the 7 remote peers'
// ping-pong hbuf (plain weak DSMEM stores, rank-rotated) + plain local store;
// __syncthreads; threads 0..7 fence + ONE remote release-arrive each.
// Consumer: single try_wait.parity acquire.cluster. No cluster barrier per
// step, no CCTL.IVALL, no per-byte tx accounting.
// ---------------------------------------------------------------------------
__global__ __launch_bounds__(RT, 1) __cluster_dims__(CL, 1, 1)
void rnn_kernel(const float* __restrict__ Wh, float* __restrict__ out)
{
    extern __shared__ float sm[];
    float* sWh  = sm;                              // [JC][HDIM]       128 KB
    float* hbuf = sm + JC * HDIM;                  // [2][BROWS][HDIM]  16 KB
    u64*   mbar = (u64*)(sm + JC * HDIM + 2 * BROWS * HDIM);  // full[2]

    const int tid = threadIdx.x;
    uint32_t rank;
    asm("mov.u32 %0, %%cluster_ctarank;" : "=r"(rank));
    const int g = blockIdx.x / CL;

    const uint32_t mb_base = smem_u32(mbar);
    if (tid == 0) {
        mbar_init(mb_base + 0, CL);   // 8 producer-CTA arrivals per step
        mbar_init(mb_base + 8, CL);
    }

    // load this CTA's Wh rows [rank*JC, +JC) once
    {
        const float4* src = (const float4*)(Wh + (size_t)rank * JC * HDIM);
        float4* dst = (float4*)sWh;
        for (int i = tid; i < JC * HDIM / 4; i += RT) dst[i] = src[i];
    }
    __syncthreads();
    CLUSTER_SYNC();   // one-time: peers' mbarriers initialized before any arrive

    const int w    = tid >> 5;
    const int lane = tid & 31;
    const int b    = lane >> 3;
    const int ojl  = rank * JC + w * 8 + (lane & 7);
    const int ob   = g * BROWS + b;

    const u64* wb2 = (const u64*)sWh + (w * 8) * (HDIM / 2) + lane;

    const uint32_t hb_base = smem_u32(hbuf);
    uint32_t peer_hb[CL];   // peer_hb[0] == self; r=1..7 remote, rank-rotated
#pragma unroll
    for (int r = 0; r < CL; r++)
        peer_hb[r] = mapa_u32(hb_base, (rank + r) & (CL - 1));
    // thread tid<8 arrives on peer (rank+tid)&7's barriers
    const uint32_t my_peer_mb = (tid < CL)
        ? mapa_u32(mb_base, (rank + tid) & (CL - 1)) : 0u;

    int ph[2] = {0, 0};   // wait-parity per buffer

    const size_t obase = (size_t)ob * HDIM + ojl;
    float xiv_next = __ldg(out + obase);   // xi' = xi + bi + bh (precomputed)

    for (int t = 1; t <= SEQ; t++) {
        const int bcur = t & 1;
        const size_t oidx = (size_t)(t - 1) * (BATCH * HDIM) + obase;

        const float xiv = xiv_next;
        if (t < SEQ) xiv_next = __ldg(out + oidx + BATCH * HDIM);

        float sum = 0.f;
        if (t > 1) {
            const int bprev = (t - 1) & 1;
            mbar_wait_cluster(mb_base + bprev * 8, ph[bprev]);
            ph[bprev] ^= 1;

            const u64* hp = (const u64*)(hbuf + bprev * BROWS * HDIM) + lane;

            u64 acc[4][8];
#pragma unroll
            for (int i = 0; i < 4; i++)
#pragma unroll
                for (int j = 0; j < 8; j++) acc[i][j] = 0ull;

#pragma unroll
            for (int d = 0; d < 8; d++) {   // k = d*64 + lane*2
                u64 hv[4], wv[8];
#pragma unroll
                for (int i = 0; i < 4; i++) hv[i] = hp[i * (HDIM / 2) + d * 32];
#pragma unroll
                for (int j = 0; j < 8; j++) wv[j] = wb2[j * (HDIM / 2) + d * 32];
#pragma unroll
                for (int i = 0; i < 4; i++)
#pragma unroll
                    for (int j = 0; j < 8; j++) acc[i][j] = fma2(hv[i], wv[j], acc[i][j]);
            }

            float v[32];
#pragma unroll
            for (int i = 0; i < 4; i++)
#pragma unroll
                for (int j = 0; j < 8; j++) {
                    float2 a = *reinterpret_cast<float2*>(&acc[i][j]);
                    v[i * 8 + j] = a.x + a.y;
                }
#pragma unroll
            for (int m = 0; m < 5; m++) {
                const int mb2 = (lane >> m) & 1;
#pragma unroll
                for (int j2 = 0; j2 < (16 >> m); j2++) {
                    float send = v[2 * j2 + 1 - mb2];
                    float recv = __shfl_xor_sync(0xffffffffu, send, 1 << m);
                    v[j2] = v[2 * j2 + mb2] + recv;
                }
            }
            sum = v[0];
        }

        const float hval = tanhf(sum + xiv);

        if (t < SEQ) {
            // push packed (j, j+1) pairs: local plain store + 7 remote DSMEM
            float nxt = __shfl_down_sync(0xffffffffu, hval, 1);
            if (!(lane & 1)) {
                float2 p2 = make_float2(hval, nxt);
                u64 pv = *reinterpret_cast<u64*>(&p2);
                const uint32_t boff = bcur * BROWS * HDIM + b * HDIM + ojl;
                *reinterpret_cast<u64*>(hbuf + boff) = pv;     // self
#pragma unroll
                for (int r = 1; r < CL; r++)
                    st_cluster_b64(peer_hb[r] + boff * 4, pv); // 7 remotes
            }
            __syncthreads();            // all lanes' pushes issued (CTA order)
            if (tid < CL) {
                fence_cluster();        // CTA's DSMEM stores cluster-visible
                mbar_arrive_remote(my_peer_mb + bcur * 8);  // 1 arrive/peer
            }
        }

        out[oidx] = hval;               // h_seq[t-1], off the dependency chain
        if (t == SEQ)
            out[(size_t)SEQ * BATCH * HDIM + obase] = hval;   // h_last
    }
}

// ---------------------------------------------------------------------------
extern "C" void kernel_launch(void* const* d_in, const int* in_sizes, int n_in,
                              void* d_out, int out_size)
{
    const float* x  = (const float*)d_in[0];
    const float* Wi = (const float*)d_in[1];
    const float* bi = (const float*)d_in[2];
    const float* Wh = (const float*)d_in[3];
    const float* bh = (const float*)d_in[4];
    float* out = (float*)d_out;

    const int XI_SMEM  = (128 * 130 + 64 * 130) * 4;                 // 99840 B
    const int RNN_SMEM = (JC * HDIM + 2 * BROWS * HDIM) * 4 + 16;    // 147472 B

    cudaFuncSetAttribute(xi_kernel,  cudaFuncAttributeMaxDynamicSharedMemorySize, XI_SMEM);
    cudaFuncSetAttribute(rnn_kernel, cudaFuncAttributeMaxDynamicSharedMemorySize, RNN_SMEM);

    xi_kernel<<<dim3(32768 / 64, HDIM / 128), 256, XI_SMEM>>>(x, Wi, bi, bh, out);
    rnn_kernel<<<NG * CL, RT, RNN_SMEM>>>(Wh, out);
}

// round 10
// speedup vs baseline: 1.9803x; 1.0715x over previous
#include <cuda_runtime.h>
#include <cstdint>
#include <cstddef>

#define SEQ    512
#define BATCH  64
#define INDIM  128
#define HDIM   512

#define CL     8            // CTAs per cluster (H split)
#define NCLUST 8            // clusters; each serves 8 batch rows (2 groups of 4)
#define GROWS  4            // rows per group
#define JC     (HDIM / CL)  // 64 j columns per CTA
#define RT     256

typedef unsigned long long u64;

__device__ __forceinline__ u64 fma2(u64 a, u64 b, u64 c) {
    u64 d;
    asm("fma.rn.f32x2 %0, %1, %2, %3;" : "=l"(d) : "l"(a), "l"(b), "l"(c));
    return d;
}
__device__ __forceinline__ uint32_t smem_u32(const void* p) {
    uint32_t a;
    asm("{ .reg .u64 t; cvta.to.shared.u64 t, %1; cvt.u32.u64 %0, t; }" : "=r"(a) : "l"(p));
    return a;
}
__device__ __forceinline__ uint32_t mapa_u32(uint32_t a, uint32_t r) {
    uint32_t d;
    asm("mapa.shared::cluster.u32 %0, %1, %2;" : "=r"(d) : "r"(a), "r"(r));
    return d;
}
__device__ __forceinline__ void mbar_init(uint32_t a, uint32_t cnt) {
    asm volatile("mbarrier.init.shared.b64 [%0], %1;" :: "r"(a), "r"(cnt) : "memory");
}
__device__ __forceinline__ void mbar_wait_cluster(uint32_t a, uint32_t parity) {
    asm volatile(
        "{\n\t"
        ".reg .pred P;\n\t"
        "WL_%=:\n\t"
        "mbarrier.try_wait.parity.acquire.cluster.shared::cta.b64 P, [%0], %1, 0x989680;\n\t"
        "@P bra.uni WD_%=;\n\t"
        "bra.uni WL_%=;\n\t"
        "WD_%=:\n\t"
        "}"
        :: "r"(a), "r"(parity) : "memory");
}
__device__ __forceinline__ void mbar_arrive_remote(uint32_t a) {
    asm volatile("mbarrier.arrive.release.cluster.shared::cluster.b64 _, [%0];"
                 :: "r"(a) : "memory");
}
__device__ __forceinline__ void fence_cluster() {
    asm volatile("fence.acq_rel.cluster;" ::: "memory");
}
__device__ __forceinline__ void st_cluster_b64(uint32_t a, u64 v) {
    asm volatile("st.shared::cluster.b64 [%0], %1;" :: "r"(a), "l"(v) : "memory");
}
#define CLUSTER_SYNC() do { \
    asm volatile("barrier.cluster.arrive.aligned;" ::: "memory"); \
    asm volatile("barrier.cluster.wait.aligned;"   ::: "memory"); \
} while (0)

// ---------------------------------------------------------------------------
// xi kernel (validated R3-R8): out[s][b][h] = x.Wi + bi + bh
// ---------------------------------------------------------------------------
__global__ __launch_bounds__(256) void xi_kernel(
    const float* __restrict__ x, const float* __restrict__ Wi,
    const float* __restrict__ bi, const float* __restrict__ bh,
    float* __restrict__ out)
{
    extern __shared__ float sm[];
    float* ws = sm;               // [128][130]
    float* xs = sm + 128 * 130;   // [64][130]

    const int tid = threadIdx.x;
    const int sb0 = blockIdx.x * 64;
    const int h0  = blockIdx.y * 128;

    for (int i = tid; i < 128 * INDIM; i += 256) {
        int r = i >> 7, k = i & 127;
        ws[r * 130 + k] = Wi[(h0 + r) * INDIM + k];
    }
    for (int i = tid; i < 64 * INDIM; i += 256) {
        int r = i >> 7, k = i & 127;
        xs[r * 130 + k] = x[(size_t)(sb0 + r) * INDIM + k];
    }
    __syncthreads();

    const int w  = tid >> 5;
    const int tx = tid & 31;

    u64 acc2[8][4];
#pragma unroll
    for (int i = 0; i < 8; i++)
#pragma unroll
        for (int j = 0; j < 4; j++) acc2[i][j] = 0ull;

    const u64* xb2 = (const u64*)xs + (w * 8) * 65;
    const u64* wb2 = (const u64*)ws;

#pragma unroll 4
    for (int kp = 0; kp < 64; kp++) {
        u64 xv[8], wv[4];
#pragma unroll
        for (int i = 0; i < 8; i++) xv[i] = xb2[i * 65 + kp];
#pragma unroll
        for (int j = 0; j < 4; j++) wv[j] = wb2[(j * 32 + tx) * 65 + kp];
#pragma unroll
        for (int i = 0; i < 8; i++)
#pragma unroll
            for (int j = 0; j < 4; j++) acc2[i][j] = fma2(xv[i], wv[j], acc2[i][j]);
    }

#pragma unroll
    for (int j = 0; j < 4; j++) {
        int h = h0 + j * 32 + tx;
        float b = bi[h] + bh[h];
#pragma unroll
        for (int i = 0; i < 8; i++) {
            float2 a = *reinterpret_cast<float2*>(&acc2[i][j]);
            out[(size_t)(sb0 + w * 8 + i) * HDIM + h] = a.x + a.y + b;
        }
    }
}

// ---------------------------------------------------------------------------
// Recurrence: 8 clusters x 8 CTAs. Each CTA holds Wh rows [rank*64,+64)
// (128KB SMEM) and serves TWO batch groups (A: rows gbase..+3, B: +4..+7),
// time-interleaved so each group's DSMEM push/arrive round trip is hidden
// under the other group's compute; every try_wait hits the fast path.
// Half-step: wait -> LDS.128 + fma.rn.f32x2 compute -> shuffle butterfly ->
// tanh -> DSMEM push (weak) -> __syncthreads -> tid<8: fence + 1 remote
// release-arrive each (count-8 barriers, ping-pong per group).
// ---------------------------------------------------------------------------
__global__ __launch_bounds__(RT, 1) __cluster_dims__(CL, 1, 1)
void rnn_kernel(const float* __restrict__ Wh, float* __restrict__ out)
{
    extern __shared__ float sm[];
    float* sWh = sm;                         // [64][512]        128 KB
    float* hbA = sm + JC * HDIM;             // [2][4][512]       16 KB
    float* hbB = hbA + 2 * GROWS * HDIM;     // [2][4][512]       16 KB
    u64*   mbar = (u64*)(hbB + 2 * GROWS * HDIM);  // A0,A1,B0,B1

    const int tid = threadIdx.x;
    uint32_t rank;
    asm("mov.u32 %0, %%cluster_ctarank;" : "=r"(rank));
    const int gbase = (blockIdx.x / CL) * 8;   // 8 batch rows per cluster

    const uint32_t mb_base = smem_u32(mbar);
    if (tid == 0) {
#pragma unroll
        for (int i = 0; i < 4; i++) mbar_init(mb_base + i * 8, CL);
    }

    {   // load Wh rows [rank*64, +64) once
        const float4* src = (const float4*)(Wh + (size_t)rank * JC * HDIM);
        float4* dst = (float4*)sWh;
        for (int i = tid; i < JC * HDIM / 4; i += RT) dst[i] = src[i];
    }
    __syncthreads();
    CLUSTER_SYNC();   // peers' mbarriers live before any arrive

    const int w    = tid >> 5;          // warp -> j octet
    const int lane = tid & 31;
    const int b    = lane >> 3;         // output row (after butterfly)
    const int ojl  = rank * JC + w * 8 + (lane & 7);   // global j index
    const int obA  = gbase + b;
    const int obB  = gbase + 4 + b;

    // weights as 16B vectors: element (j*128 + d*32 + lane) covers k=4 floats
    const ulonglong2* wv2 = (const ulonglong2*)sWh + (w * 8) * (HDIM / 4) + lane;

    const uint32_t hbA_base = smem_u32(hbA);
    uint32_t peer_hbA[CL];
#pragma unroll
    for (int r = 0; r < CL; r++)
        peer_hbA[r] = mapa_u32(hbA_base, (rank + r) & (CL - 1));
    const uint32_t HB_DELTA = 2 * GROWS * HDIM * 4;   // hbB - hbA in bytes
    const uint32_t my_peer_mb = (tid < CL)
        ? mapa_u32(mb_base, (rank + tid) & (CL - 1)) : 0u;

    int phA[2] = {0, 0}, phB[2] = {0, 0};

    const size_t obaseA = (size_t)obA * HDIM + ojl;
    const size_t obaseB = (size_t)obB * HDIM + ojl;
    float xiA = __ldg(out + obaseA);
    float xiB = __ldg(out + obaseB);

    for (int t = 1; t <= SEQ; t++) {
        const int bcur  = t & 1;
        const int bprev = 1 - bcur;
        const size_t step_off = (size_t)(t - 1) * (BATCH * HDIM);

        // ================= group A =================
        float sumA = 0.f;
        if (t > 1) {
            mbar_wait_cluster(mb_base + bprev * 8, phA[bprev]);   // A barrier bprev
            phA[bprev] ^= 1;
            const ulonglong2* hp = (const ulonglong2*)(hbA + bprev * GROWS * HDIM) + lane;

            u64 acc[4][8];
#pragma unroll
            for (int i = 0; i < 4; i++)
#pragma unroll
                for (int j = 0; j < 8; j++) acc[i][j] = 0ull;
#pragma unroll
            for (int d = 0; d < 4; d++) {   // k = d*128 + lane*4
                ulonglong2 hv[4], wv[8];
#pragma unroll
                for (int i = 0; i < 4; i++) hv[i] = hp[i * (HDIM / 4) + d * 32];
#pragma unroll
                for (int j = 0; j < 8; j++) wv[j] = wv2[j * (HDIM / 4) + d * 32];
#pragma unroll
                for (int i = 0; i < 4; i++)
#pragma unroll
                    for (int j = 0; j < 8; j++) {
                        acc[i][j] = fma2(hv[i].x, wv[j].x, acc[i][j]);
                        acc[i][j] = fma2(hv[i].y, wv[j].y, acc[i][j]);
                    }
            }
            float v[32];
#pragma unroll
            for (int i = 0; i < 4; i++)
#pragma unroll
                for (int j = 0; j < 8; j++) {
                    float2 a = *reinterpret_cast<float2*>(&acc[i][j]);
                    v[i * 8 + j] = a.x + a.y;
                }
#pragma unroll
            for (int m = 0; m < 5; m++) {
                const int mb2 = (lane >> m) & 1;
#pragma unroll
                for (int j2 = 0; j2 < (16 >> m); j2++) {
                    float send = v[2 * j2 + 1 - mb2];
                    float recv = __shfl_xor_sync(0xffffffffu, send, 1 << m);
                    v[j2] = v[2 * j2 + mb2] + recv;
                }
            }
            sumA = v[0];
        }
        const float hA = tanhf(sumA + xiA);
        if (t < SEQ) xiA = __ldg(out + step_off + BATCH * HDIM + obaseA);

        if (t < SEQ) {
            float nxt = __shfl_down_sync(0xffffffffu, hA, 1);
            if (!(lane & 1)) {
                float2 p2 = make_float2(hA, nxt);
                u64 pv = *reinterpret_cast<u64*>(&p2);
                const uint32_t boff = bcur * GROWS * HDIM + b * HDIM + ojl;
                *reinterpret_cast<u64*>(hbA + boff) = pv;      // self, plain
#pragma unroll
                for (int r = 1; r < CL; r++)
                    st_cluster_b64(peer_hbA[r] + boff * 4, pv);
            }
            __syncthreads();
            if (tid < CL) {
                fence_cluster();
                mbar_arrive_remote(my_peer_mb + bcur * 8);     // A barrier bcur
            }
        }
        out[step_off + obaseA] = hA;
        if (t == SEQ) out[(size_t)SEQ * BATCH * HDIM + obaseA] = hA;

        // ================= group B ================= (hides A's fabric RT)
        float sumB = 0.f;
        if (t > 1) {
            mbar_wait_cluster(mb_base + 16 + bprev * 8, phB[bprev]);  // B barrier bprev
            phB[bprev] ^= 1;
            const ulonglong2* hp = (const ulonglong2*)(hbB + bprev * GROWS * HDIM) + lane;

            u64 acc[4][8];
#pragma unroll
            for (int i = 0; i < 4; i++)
#pragma unroll
                for (int j = 0; j < 8; j++) acc[i][j] = 0ull;
#pragma unroll
            for (int d = 0; d < 4; d++) {
                ulonglong2 hv[4], wv[8];
#pragma unroll
                for (int i = 0; i < 4; i++) hv[i] = hp[i * (HDIM / 4) + d * 32];
#pragma unroll
                for (int j = 0; j < 8; j++) wv[j] = wv2[j * (HDIM / 4) + d * 32];
#pragma unroll
                for (int i = 0; i < 4; i++)
#pragma unroll
                    for (int j = 0; j < 8; j++) {
                        acc[i][j] = fma2(hv[i].x, wv[j].x, acc[i][j]);
                        acc[i][j] = fma2(hv[i].y, wv[j].y, acc[i][j]);
                    }
            }
            float v[32];
#pragma unroll
            for (int i = 0; i < 4; i++)
#pragma unroll
                for (int j = 0; j < 8; j++) {
                    float2 a = *reinterpret_cast<float2*>(&acc[i][j]);
                    v[i * 8 + j] = a.x + a.y;
                }
#pragma unroll
            for (int m = 0; m < 5; m++) {
                const int mb2 = (lane >> m) & 1;
#pragma unroll
                for (int j2 = 0; j2 < (16 >> m); j2++) {
                    float send = v[2 * j2 + 1 - mb2];
                    float recv = __shfl_xor_sync(0xffffffffu, send, 1 << m);
                    v[j2] = v[2 * j2 + mb2] + recv;
                }
            }
            sumB = v[0];
        }
        const float hB = tanhf(sumB + xiB);
        if (t < SEQ) xiB = __ldg(out + step_off + BATCH * HDIM + obaseB);

        if (t < SEQ) {
            float nxt = __shfl_down_sync(0xffffffffu, hB, 1);
            if (!(lane & 1)) {
                float2 p2 = make_float2(hB, nxt);
                u64 pv = *reinterpret_cast<u64*>(&p2);
                const uint32_t boff = bcur * GROWS * HDIM + b * HDIM + ojl;
                *reinterpret_cast<u64*>(hbB + boff) = pv;      // self, plain
#pragma unroll
                for (int r = 1; r < CL; r++)
                    st_cluster_b64(peer_hbA[r] + HB_DELTA + boff * 4, pv);
            }
            __syncthreads();
            if (tid < CL) {
                fence_cluster();
                mbar_arrive_remote(my_peer_mb + 16 + bcur * 8);   // B barrier bcur
            }
        }
        out[step_off + obaseB] = hB;
        if (t == SEQ) out[(size_t)SEQ * BATCH * HDIM + obaseB] = hB;
    }
}

// ---------------------------------------------------------------------------
extern "C" void kernel_launch(void* const* d_in, const int* in_sizes, int n_in,
                              void* d_out, int out_size)
{
    const float* x  = (const float*)d_in[0];
    const float* Wi = (const float*)d_in[1];
    const float* bi = (const float*)d_in[2];
    const float* Wh = (const float*)d_in[3];
    const float* bh = (const float*)d_in[4];
    float* out = (float*)d_out;

    const int XI_SMEM  = (128 * 130 + 64 * 130) * 4;                 // 99840 B
    const int RNN_SMEM = (JC * HDIM + 4 * GROWS * HDIM) * 4 + 32;    // 163872 B

    cudaFuncSetAttribute(xi_kernel,  cudaFuncAttributeMaxDynamicSharedMemorySize, XI_SMEM);
    cudaFuncSetAttribute(rnn_kernel, cudaFuncAttributeMaxDynamicSharedMemorySize, RNN_SMEM);

    xi_kernel<<<dim3(32768 / 64, HDIM / 128), 256, XI_SMEM>>>(x, Wi, bi, bh, out);
    rnn_kernel<<<NCLUST * CL, RT, RNN_SMEM>>>(Wh, out);
}